// round 1
// baseline (speedup 1.0000x reference)
#include <cuda_runtime.h>

// ---------------- problem constants ----------------
#define NLOC   6400        // 80*80 query/key locations per batch
#define DH     144         // Ci*K*K = 16*9
#define NPIX   25600       // 160*160
#define CIN    64
#define CI     16
#define DD     8
#define MIDOFF (4*NPIX)    // mid = D/2 = 4

typedef unsigned long long u64;

// ---------------- packed f32x2 helpers ----------------
__device__ __forceinline__ u64 pk2(float lo, float hi){
    u64 r; asm("mov.b64 %0,{%1,%2};" : "=l"(r) : "f"(lo), "f"(hi)); return r;
}
__device__ __forceinline__ void fma2(u64 &a, u64 x, u64 y){
    asm("fma.rn.f32x2 %0,%1,%2,%0;" : "+l"(a) : "l"(x), "l"(y));
}
__device__ __forceinline__ u64 mul2(u64 x, u64 y){
    u64 r; asm("mul.rn.f32x2 %0,%1,%2;" : "=l"(r) : "l"(x), "l"(y)); return r;
}
__device__ __forceinline__ float sumhl(u64 a){
    float l, h; asm("mov.b64 {%0,%1}, %2;" : "=f"(l), "=f"(h) : "l"(a)); return l + h;
}

// ---------------- scratch (static device globals; no allocs) ----------------
__device__ float g_X[2*3*CI*NPIX];     // conv outputs at mid slice: [batch][mat(g,theta,phi)][ci][pix]
__device__ float g_Q[2*NLOC*DH];       // Q pre-scaled by 10*log2(e)
__device__ float g_K[2*NLOC*DH];
__device__ float g_V[2*NLOC*DH];
__device__ float g_Z[2*NLOC*DH];       // attention output
__device__ float g_Y[2*CIN*NPIX];      // W-conv of folded zi2 (+bias)

// ================= K1: 1x1 conv at mid slice (3 projections) =================
__global__ void conv_mid_kernel(const float* __restrict__ b,
                                const float* __restrict__ gw, const float* __restrict__ gb,
                                const float* __restrict__ tw, const float* __restrict__ tb,
                                const float* __restrict__ pw, const float* __restrict__ pb)
{
    __shared__ float ws[3*CI*CIN];
    __shared__ float bs[3*CI];
    int tid = threadIdx.x;
    for (int i = tid; i < CI*CIN; i += 256){
        ws[i] = gw[i]; ws[CI*CIN + i] = tw[i]; ws[2*CI*CIN + i] = pw[i];
    }
    if (tid < CI){ bs[tid] = gb[tid]; bs[CI+tid] = tb[tid]; bs[2*CI+tid] = pb[tid]; }
    __syncthreads();

    int pix   = blockIdx.x*256 + tid;          // 25600 = 100*256 exact
    int batch = blockIdx.y;
    const float* bp = b + (size_t)batch*CIN*DD*NPIX + MIDOFF + pix;

    float acc[48];
    #pragma unroll
    for (int i = 0; i < 48; i++) acc[i] = bs[i];

    for (int c = 0; c < CIN; c++){
        float v = bp[(size_t)c*DD*NPIX];
        #pragma unroll
        for (int m = 0; m < 3; m++)
            #pragma unroll
            for (int ci = 0; ci < CI; ci++)
                acc[m*CI + ci] += ws[m*CI*CIN + ci*CIN + c] * v;
    }
    float* xo = g_X + (size_t)batch*3*CI*NPIX;
    #pragma unroll
    for (int i = 0; i < 48; i++)
        xo[(size_t)i*NPIX + pix] = acc[i];
}

// ================= K2: unfold to patch matrices Q/K/V [6400][144] =================
__global__ void build_patches_kernel()
{
    int batch = blockIdx.z;
    int mat   = blockIdx.y;                    // 0=g->Q, 1=theta->V, 2=phi->K
    int idx   = blockIdx.x*256 + threadIdx.x;  // 921600 = 3600*256 exact
    int l = idx / DH, j = idx % DH;
    int ci = j / 9, t = j % 9, kr = t/3, kc = t%3;
    int ih = l / 80, iw = l % 80;
    int r = ih*2 + kr - 1, c = iw*2 + kc - 1;
    const float* X = g_X + ((size_t)(batch*3 + mat))*CI*NPIX;
    float v = 0.f;
    if ((unsigned)r < 160u && (unsigned)c < 160u) v = X[ci*NPIX + r*160 + c];
    float scale = (mat == 0) ? 14.4269504088896340736f : 1.0f;  // 10 * log2(e)
    float* dst = (mat == 0 ? g_Q : (mat == 1 ? g_V : g_K)) + (size_t)batch*NLOC*DH;
    dst[idx] = v * scale;
}

// ================= K3: flash attention, fp32 + packed f32x2 =================
// smem layout (floats)
#define SM_QS 0            // [64][144]
#define SM_KS 9216         // 16 groups * 578 (pair-grouped, conflict-free)
#define SM_VS 18464        // [64][144]
#define SM_PS 27680        // [64][68]
#define SM_M  32032
#define SM_L  32096
#define SM_SC 32160
#define SM_FLOATS 32224
#define SM_BYTES (SM_FLOATS*4)

__global__ __launch_bounds__(256, 1) void flash_kernel()
{
    extern __shared__ float sm[];
    int tid   = threadIdx.x;
    int batch = blockIdx.y;
    int qb    = blockIdx.x;

    const float* Qg = g_Q + (size_t)batch*NLOC*DH;
    const float* Kg = g_K + (size_t)batch*NLOC*DH;
    const float* Vg = g_V + (size_t)batch*NLOC*DH;
    float*       Zg = g_Z + (size_t)batch*NLOC*DH;

    // load Q tile (plain layout)
    {
        const float4* qsrc = (const float4*)(Qg + (size_t)qb*64*DH);
        float4* qdst = (float4*)(sm + SM_QS);
        for (int t = tid; t < 64*DH/4; t += 256) qdst[t] = qsrc[t];
    }
    if (tid < 64){ sm[SM_M + tid] = -1e30f; sm[SM_L + tid] = 0.f; }

    const int tx  = tid & 15, ty  = tid >> 4;   // S-phase: 4 rows x 4 cols each
    const int txv = tid & 7,  tyv = tid >> 3;   // PV-phase: 2 rows x 18 cols each
    const int r0 = 2*tyv, r1 = r0 + 1, cb = txv*18;

    u64 oacc[2][9];
    #pragma unroll
    for (int i = 0; i < 2; i++)
        #pragma unroll
        for (int p = 0; p < 9; p++) oacc[i][p] = 0ull;

    for (int kb = 0; kb < 100; kb++){
        if (kb) __syncthreads();     // PV of prev iter done before overwriting K/V

        // --- load V tile (plain) ---
        {
            const float4* vsrc = (const float4*)(Vg + (size_t)kb*64*DH);
            float4* vdst = (float4*)(sm + SM_VS);
            for (int t = tid; t < 64*DH/4; t += 256) vdst[t] = vsrc[t];
        }
        // --- load K tile into pair-grouped layout ---
        {
            const float4* ksrc = (const float4*)(Kg + (size_t)kb*64*DH);
            for (int t = tid; t < 64*DH/4; t += 256){
                float4 v = ksrc[t];
                int c  = (t*4)/DH, k0 = (t*4)%DH;     // k0 in {0,4,...,140}
                int g  = c >> 2,   j  = c & 3;
                float* kd = sm + SM_KS + g*578 + (((k0>>1)*4 + j) << 1);
                kd[0] = v.x; kd[1] = v.y; kd[8] = v.z; kd[9] = v.w;
            }
        }
        __syncthreads();

        // --- S = Q K^T, packed over k ---
        u64 acc[4][4];
        #pragma unroll
        for (int i = 0; i < 4; i++)
            #pragma unroll
            for (int j = 0; j < 4; j++) acc[i][j] = 0ull;

        const u64* q0 = (const u64*)(sm + SM_QS + (4*ty+0)*DH);
        const u64* q1 = (const u64*)(sm + SM_QS + (4*ty+1)*DH);
        const u64* q2 = (const u64*)(sm + SM_QS + (4*ty+2)*DH);
        const u64* q3 = (const u64*)(sm + SM_QS + (4*ty+3)*DH);
        const u64* kp = (const u64*)(sm + SM_KS + tx*578);

        #pragma unroll 4
        for (int k = 0; k < 72; k++){
            u64 qv0 = q0[k], qv1 = q1[k], qv2 = q2[k], qv3 = q3[k];
            u64 kv0 = kp[4*k+0], kv1 = kp[4*k+1], kv2 = kp[4*k+2], kv3 = kp[4*k+3];
            fma2(acc[0][0], qv0, kv0); fma2(acc[0][1], qv0, kv1);
            fma2(acc[0][2], qv0, kv2); fma2(acc[0][3], qv0, kv3);
            fma2(acc[1][0], qv1, kv0); fma2(acc[1][1], qv1, kv1);
            fma2(acc[1][2], qv1, kv2); fma2(acc[1][3], qv1, kv3);
            fma2(acc[2][0], qv2, kv0); fma2(acc[2][1], qv2, kv1);
            fma2(acc[2][2], qv2, kv2); fma2(acc[2][3], qv2, kv3);
            fma2(acc[3][0], qv3, kv0); fma2(acc[3][1], qv3, kv1);
            fma2(acc[3][2], qv3, kv2); fma2(acc[3][3], qv3, kv3);
        }

        // --- online softmax (rows 4*ty .. 4*ty+3, reduce over 16 tx lanes) ---
        #pragma unroll
        for (int i = 0; i < 4; i++){
            float s0 = sumhl(acc[i][0]), s1 = sumhl(acc[i][1]);
            float s2 = sumhl(acc[i][2]), s3 = sumhl(acc[i][3]);
            float mx = fmaxf(fmaxf(s0, s1), fmaxf(s2, s3));
            mx = fmaxf(mx, __shfl_xor_sync(0xffffffffu, mx, 1, 16));
            mx = fmaxf(mx, __shfl_xor_sync(0xffffffffu, mx, 2, 16));
            mx = fmaxf(mx, __shfl_xor_sync(0xffffffffu, mx, 4, 16));
            mx = fmaxf(mx, __shfl_xor_sync(0xffffffffu, mx, 8, 16));
            int r = 4*ty + i;
            float mo = sm[SM_M + r];
            float mn = fmaxf(mo, mx);
            float p0 = exp2f(s0 - mn), p1 = exp2f(s1 - mn);
            float p2 = exp2f(s2 - mn), p3 = exp2f(s3 - mn);
            float rs = (p0 + p1) + (p2 + p3);
            rs += __shfl_xor_sync(0xffffffffu, rs, 1, 16);
            rs += __shfl_xor_sync(0xffffffffu, rs, 2, 16);
            rs += __shfl_xor_sync(0xffffffffu, rs, 4, 16);
            rs += __shfl_xor_sync(0xffffffffu, rs, 8, 16);
            if (tx == 0){
                float sc = exp2f(mo - mn);
                sm[SM_SC + r] = sc;
                sm[SM_L  + r] = sm[SM_L + r]*sc + rs;
                sm[SM_M  + r] = mn;
            }
            ((float4*)(sm + SM_PS + r*68))[tx] = make_float4(p0, p1, p2, p3);
        }
        __syncthreads();

        // --- O = diag(sc) O + P V  (each thread: rows r0,r1; 9 col-pairs at cb) ---
        {
            float sa = sm[SM_SC + r0], sb = sm[SM_SC + r1];
            u64 sA = pk2(sa, sa), sB = pk2(sb, sb);
            #pragma unroll
            for (int p = 0; p < 9; p++){
                oacc[0][p] = mul2(oacc[0][p], sA);
                oacc[1][p] = mul2(oacc[1][p], sB);
            }
            const float* ps0 = sm + SM_PS + r0*68;
            const float* ps1 = sm + SM_PS + r1*68;
            #pragma unroll 2
            for (int c = 0; c < 64; c++){
                float pa = ps0[c], pb = ps1[c];
                u64 pA = pk2(pa, pa), pB = pk2(pb, pb);
                const u64* vr = (const u64*)(sm + SM_VS + c*DH + cb);
                #pragma unroll
                for (int p = 0; p < 9; p++){
                    u64 vv = vr[p];
                    fma2(oacc[0][p], pA, vv);
                    fma2(oacc[1][p], pB, vv);
                }
            }
        }
    }

    // --- epilogue: normalize by l and store ---
    float inv0 = 1.f / sm[SM_L + r0];
    float inv1 = 1.f / sm[SM_L + r1];
    u64 i0 = pk2(inv0, inv0), i1 = pk2(inv1, inv1);
    u64* z0 = (u64*)(Zg + (size_t)(qb*64 + r0)*DH + cb);
    u64* z1 = (u64*)(Zg + (size_t)(qb*64 + r1)*DH + cb);
    #pragma unroll
    for (int p = 0; p < 9; p++){
        z0[p] = mul2(oacc[0][p], i0);
        z1[p] = mul2(oacc[1][p], i1);
    }
}

// ================= K4: fold (overlap-add + count normalize) + W conv =================
__global__ void fold_w_kernel(const float* __restrict__ Ww, const float* __restrict__ Wb)
{
    __shared__ float ws[CIN*CI];
    __shared__ float wb[CIN];
    int tid = threadIdx.x;
    for (int i = tid; i < CIN*CI; i += 256) ws[i] = Ww[i];
    if (tid < CIN) wb[tid] = Wb[tid];
    __syncthreads();

    int pix   = blockIdx.x*256 + tid;
    int batch = blockIdx.y;
    int h = pix / 160, w = pix % 160;

    int krs[2], ihs[2], nr = 0;
    if (!(h & 1)){ krs[0] = 1; ihs[0] = h >> 1; nr = 1; }
    else {
        if (h < 159){ krs[nr] = 0; ihs[nr] = (h+1) >> 1; nr++; }
        krs[nr] = 2; ihs[nr] = (h-1) >> 1; nr++;
    }
    int kcs[2], iws[2], nc = 0;
    if (!(w & 1)){ kcs[0] = 1; iws[0] = w >> 1; nc = 1; }
    else {
        if (w < 159){ kcs[nc] = 0; iws[nc] = (w+1) >> 1; nc++; }
        kcs[nc] = 2; iws[nc] = (w-1) >> 1; nc++;
    }

    const float* Z = g_Z + (size_t)batch*NLOC*DH;
    float acc[CI];
    #pragma unroll
    for (int ci = 0; ci < CI; ci++) acc[ci] = 0.f;

    for (int a = 0; a < nr; a++)
        for (int bb = 0; bb < nc; bb++){
            int l = ihs[a]*80 + iws[bb];
            const float* zp = Z + (size_t)l*DH + krs[a]*3 + kcs[bb];
            #pragma unroll
            for (int ci = 0; ci < CI; ci++) acc[ci] += zp[ci*9];
        }
    float inv = 1.f / (float)(nr*nc);
    #pragma unroll
    for (int ci = 0; ci < CI; ci++) acc[ci] *= inv;

    float* Y = g_Y + (size_t)batch*CIN*NPIX + pix;
    #pragma unroll 4
    for (int c = 0; c < CIN; c++){
        float s = wb[c];
        #pragma unroll
        for (int ci = 0; ci < CI; ci++) s += ws[c*CI + ci]*acc[ci];
        Y[(size_t)c*NPIX] = s;
    }
}

// ================= K5: out = b + Y (broadcast over D) =================
__global__ void epilogue_kernel(const float* __restrict__ b, float* __restrict__ out)
{
    size_t i = (size_t)blockIdx.x*256 + threadIdx.x;      // float4 index, 6,553,600 total
    size_t e = i*4;
    const size_t per_batch = (size_t)CIN*DD*NPIX;
    int batch = (int)(e / per_batch);
    size_t rem  = e % per_batch;
    int c  = (int)(rem / ((size_t)DD*NPIX));
    int pix = (int)(rem % NPIX);                           // multiple of 4

    float4 bv = ((const float4*)b)[i];
    const float4* y4 = (const float4*)(g_Y + (size_t)batch*CIN*NPIX + (size_t)c*NPIX + pix);
    float4 yv = *y4;
    ((float4*)out)[i] = make_float4(bv.x + yv.x, bv.y + yv.y, bv.z + yv.z, bv.w + yv.w);
}

// ================= launch =================
extern "C" void kernel_launch(void* const* d_in, const int* in_sizes, int n_in,
                              void* d_out, int out_size)
{
    const float* b   = (const float*)d_in[0];
    const float* gw  = (const float*)d_in[1];
    const float* gb  = (const float*)d_in[2];
    const float* tw  = (const float*)d_in[3];
    const float* tb  = (const float*)d_in[4];
    const float* pw  = (const float*)d_in[5];
    const float* pb  = (const float*)d_in[6];
    const float* Ww  = (const float*)d_in[7];
    const float* Wb  = (const float*)d_in[8];
    float* out = (float*)d_out;

    cudaFuncSetAttribute(flash_kernel, cudaFuncAttributeMaxDynamicSharedMemorySize, SM_BYTES);

    conv_mid_kernel<<<dim3(100, 2), 256>>>(b, gw, gb, tw, tb, pw, pb);
    build_patches_kernel<<<dim3(3600, 3, 2), 256>>>();
    flash_kernel<<<dim3(100, 2), 256, SM_BYTES>>>();
    fold_w_kernel<<<dim3(100, 2), 256>>>(Ww, Wb);
    epilogue_kernel<<<25600, 256>>>(b, out);
}